// round 1
// baseline (speedup 1.0000x reference)
#include <cuda_runtime.h>
#include <math.h>

#define HF 200
#define WF 200
#define CH 256
#define HO 7
#define WO 7
#define SUBS 2
#define HS (HO * SUBS)   // 14
#define WS (WO * SUBS)   // 14

// Channels-last scratch copy of the feature map: featT[(y*WF + x)*CH + c]
__device__ float g_featT[HF * WF * CH];  // 41 MB static scratch (allowed)

// ---------------------------------------------------------------------------
// Kernel 1: transpose (C, H*W) -> (H*W, C) via 32x32 smem tiles
// in:  features[c * (HF*WF) + p]
// out: g_featT[p * CH + c]
// ---------------------------------------------------------------------------
__global__ void transpose_kernel(const float* __restrict__ in) {
    __shared__ float tile[32][33];
    const int p0 = blockIdx.x * 32;   // spatial (40000 / 32 = 1250 blocks)
    const int c0 = blockIdx.y * 32;   // channel (256 / 32 = 8 blocks)
    const int tx = threadIdx.x;       // 0..31
    const int ty = threadIdx.y;       // 0..7

#pragma unroll
    for (int i = 0; i < 32; i += 8) {
        // coalesced read along p
        tile[ty + i][tx] = in[(size_t)(c0 + ty + i) * (HF * WF) + (p0 + tx)];
    }
    __syncthreads();
#pragma unroll
    for (int i = 0; i < 32; i += 8) {
        // coalesced write along c
        g_featT[(size_t)(p0 + ty + i) * CH + (c0 + tx)] = tile[tx][ty + i];
    }
}

// ---------------------------------------------------------------------------
// Kernel 2: ROI align + 2x2 max subsample.
// Grid: (N, HO). Block: 256 threads.
// Each block handles one (roi n, output row ph): 7 output cols x 256 channels.
// Work item = (pw, c4) where c4 indexes a float4 channel chunk (64 chunks).
// item = pw*64 + c4  -> consecutive threads share pw, walk c4 => 512B
// contiguous loads per warp per corner.
// ---------------------------------------------------------------------------
__global__ __launch_bounds__(256) void roialign_kernel(
    const float* __restrict__ rois,
    const float* __restrict__ img_size,
    float* __restrict__ out)
{
    const int n  = blockIdx.x;
    const int ph = blockIdx.y;
    const int tid = threadIdx.x;

    __shared__ float s_out[WO][CH + 4];  // +4 pad: keeps 16B alignment, breaks bank stride
    __shared__ int   s_iu[2], s_idn[2];
    __shared__ float s_fy[2];
    __shared__ int   s_il[WS], s_ir[WS];
    __shared__ float s_fx[WS];

    // --- per-ROI geometry (cheap; every thread computes the scalars) ---
    const float y1 = rois[n * 4 + 0];
    const float x1 = rois[n * 4 + 1];
    const float y2 = rois[n * 4 + 2];
    const float x2 = rois[n * 4 + 3];
    const float Hs = img_size[0];
    const float Ws_ = img_size[1];
    const float sy_scale = (HF - 1.0f) / (Hs - 1.0f);
    const float sx_scale = (WF - 1.0f) / (Ws_ - 1.0f);
    const float r0 = y1 * sy_scale;
    const float r1 = x1 * sx_scale;
    const float r2 = y2 * sy_scale;
    const float r3 = x2 * sx_scale;
    const float h_step = (r2 - r0) / (float)HS;
    const float w_step = (r3 - r1) / (float)WS;

    // --- precompute sample coordinate tables for this block ---
    if (tid < 2) {
        const int ys = ph * SUBS + tid;
        const float yy = ((float)ys + 0.5f) * h_step + r0;
        const float fl = floorf(yy);
        s_iu[tid]  = (int)fl;
        s_idn[tid] = (int)ceilf(yy);
        s_fy[tid]  = yy - fl;
    } else if (tid >= 32 && tid < 32 + WS) {
        const int xs = tid - 32;
        const float xx = ((float)xs + 0.5f) * w_step + r1;
        const float fl = floorf(xx);
        s_il[xs] = (int)fl;
        s_ir[xs] = (int)ceilf(xx);
        s_fx[xs] = xx - fl;
    }
    __syncthreads();

    // --- main work: 7 * 64 = 448 items over 256 threads ---
    for (int item = tid; item < WO * (CH / 4); item += 256) {
        const int pw = item >> 6;        // / 64
        const int c4 = item & 63;        // % 64

        float4 best = make_float4(-3.0e38f, -3.0e38f, -3.0e38f, -3.0e38f);

#pragma unroll
        for (int sy = 0; sy < SUBS; sy++) {
            const int   iu  = s_iu[sy];
            const int   idn = s_idn[sy];
            const float fy  = s_fy[sy];
#pragma unroll
            for (int sx = 0; sx < SUBS; sx++) {
                const int   xs = pw * SUBS + sx;
                const int   il = s_il[xs];
                const int   ir = s_ir[xs];
                const float fx = s_fx[xs];

                const float4* p_ul = (const float4*)&g_featT[((size_t)iu  * WF + il) * CH] + c4;
                const float4* p_ur = (const float4*)&g_featT[((size_t)iu  * WF + ir) * CH] + c4;
                const float4* p_dl = (const float4*)&g_featT[((size_t)idn * WF + il) * CH] + c4;
                const float4* p_dr = (const float4*)&g_featT[((size_t)idn * WF + ir) * CH] + c4;

                const float4 v_ul = *p_ul;
                const float4 v_ur = *p_ur;
                const float4 v_dl = *p_dl;
                const float4 v_dr = *p_dr;

                const float w_ul = (1.0f - fy) * (1.0f - fx);
                const float w_dl = fy * (1.0f - fx);
                const float w_ur = (1.0f - fy) * fx;
                const float w_dr = fy * fx;

                float4 v;
                v.x = v_ul.x * w_ul + v_dl.x * w_dl + v_ur.x * w_ur + v_dr.x * w_dr;
                v.y = v_ul.y * w_ul + v_dl.y * w_dl + v_ur.y * w_ur + v_dr.y * w_dr;
                v.z = v_ul.z * w_ul + v_dl.z * w_dl + v_ur.z * w_ur + v_dr.z * w_dr;
                v.w = v_ul.w * w_ul + v_dl.w * w_dl + v_ur.w * w_ur + v_dr.w * w_dr;

                best.x = fmaxf(best.x, v.x);
                best.y = fmaxf(best.y, v.y);
                best.z = fmaxf(best.z, v.z);
                best.w = fmaxf(best.w, v.w);
            }
        }

        const int c = c4 * 4;
        s_out[pw][c + 0] = best.x;
        s_out[pw][c + 1] = best.y;
        s_out[pw][c + 2] = best.z;
        s_out[pw][c + 3] = best.w;
    }
    __syncthreads();

    // --- staged writeback: out[((n*CH + c)*HO + ph)*WO + pw] ---
    float* outp = out + ((size_t)n * CH * HO + ph) * WO;
    for (int i = tid; i < CH * WO; i += 256) {
        const int c  = i / WO;
        const int pw = i - c * WO;
        outp[(size_t)c * (HO * WO) + pw] = s_out[pw][c];
    }
}

extern "C" void kernel_launch(void* const* d_in, const int* in_sizes, int n_in,
                              void* d_out, int out_size) {
    const float* features = (const float*)d_in[0];  // (1, 256, 200, 200)
    const float* rois     = (const float*)d_in[1];  // (512, 4)
    const float* img_size = (const float*)d_in[2];  // (2,)
    float* out = (float*)d_out;                     // (512, 256, 7, 7)

    const int n_rois = in_sizes[1] / 4;

    dim3 tgrid(HF * WF / 32, CH / 32);
    dim3 tblock(32, 8);
    transpose_kernel<<<tgrid, tblock>>>(features);

    dim3 rgrid(n_rois, HO);
    roialign_kernel<<<rgrid, 256>>>(rois, img_size, out);
}

// round 2
// speedup vs baseline: 1.3182x; 1.3182x over previous
#include <cuda_runtime.h>
#include <cuda_fp16.h>
#include <math.h>

#define HF 200
#define WF 200
#define CH 256
#define HO 7
#define WO 7
#define SUBS 2
#define HS (HO * SUBS)   // 14
#define WS (WO * SUBS)   // 14

// Channels-last fp16 scratch copy: g_featTh[(y*WF + x)*CH + c]  (20.5 MB)
__device__ __half g_featTh[HF * WF * CH];

// ---------------------------------------------------------------------------
// Kernel 1: transpose (C, H*W) f32 -> (H*W, C) fp16 via 32x32 smem tiles
// ---------------------------------------------------------------------------
__global__ void transpose_kernel(const float* __restrict__ in) {
    __shared__ float tile[32][33];
    const int p0 = blockIdx.x * 32;   // spatial
    const int c0 = blockIdx.y * 32;   // channel
    const int tx = threadIdx.x;       // 0..31
    const int ty = threadIdx.y;       // 0..7

#pragma unroll
    for (int i = 0; i < 32; i += 8) {
        tile[ty + i][tx] = in[(size_t)(c0 + ty + i) * (HF * WF) + (p0 + tx)];
    }
    __syncthreads();

    // write phase: half2 stores (pairs of channels), 512 half2 items per tile
    const int tid = ty * 32 + tx;     // 0..255
#pragma unroll
    for (int it = 0; it < 2; it++) {
        const int idx = tid + it * 256;        // 0..511
        const int p_local = idx >> 4;          // /16 : 0..31
        const int k = idx & 15;                // pair index 0..15
        __half2 h = __floats2half2_rn(tile[2 * k][p_local], tile[2 * k + 1][p_local]);
        *(__half2*)&g_featTh[(size_t)(p0 + p_local) * CH + c0 + 2 * k] = h;
    }
}

// ---------------------------------------------------------------------------
// Kernel 2: ROI align + 2x2 max subsample, fp16 gathers.
// Grid: (N, HO). Block: 256 threads; 224 active work items = 7 pw x 32 c8.
// Each item owns 8 channels (one 16B uint4 of halves) for one output col.
// Consecutive threads walk c8 => 512B contiguous per corner per warp.
// ---------------------------------------------------------------------------
__global__ __launch_bounds__(256) void roialign_kernel(
    const float* __restrict__ rois,
    const float* __restrict__ img_size,
    float* __restrict__ out)
{
    const int n  = blockIdx.x;
    const int ph = blockIdx.y;
    const int tid = threadIdx.x;

    __shared__ float s_out[WO][CH + 4];
    __shared__ int   s_iu[2], s_idn[2];
    __shared__ float s_fy[2];
    __shared__ int   s_il[WS], s_ir[WS];
    __shared__ float s_fx[WS];

    // --- per-ROI geometry ---
    const float y1 = rois[n * 4 + 0];
    const float x1 = rois[n * 4 + 1];
    const float y2 = rois[n * 4 + 2];
    const float x2 = rois[n * 4 + 3];
    const float Hi = img_size[0];
    const float Wi = img_size[1];
    const float sy_scale = (HF - 1.0f) / (Hi - 1.0f);
    const float sx_scale = (WF - 1.0f) / (Wi - 1.0f);
    const float r0 = y1 * sy_scale;
    const float r1 = x1 * sx_scale;
    const float r2 = y2 * sy_scale;
    const float r3 = x2 * sx_scale;
    const float h_step = (r2 - r0) / (float)HS;
    const float w_step = (r3 - r1) / (float)WS;

    if (tid < 2) {
        const int ys = ph * SUBS + tid;
        const float yy = ((float)ys + 0.5f) * h_step + r0;
        const float fl = floorf(yy);
        s_iu[tid]  = (int)fl;
        s_idn[tid] = (int)ceilf(yy);
        s_fy[tid]  = yy - fl;
    } else if (tid >= 32 && tid < 32 + WS) {
        const int xs = tid - 32;
        const float xx = ((float)xs + 0.5f) * w_step + r1;
        const float fl = floorf(xx);
        s_il[xs] = (int)fl;
        s_ir[xs] = (int)ceilf(xx);
        s_fx[xs] = xx - fl;
    }
    __syncthreads();

    // --- main work: 224 items, single pass ---
    if (tid < WO * (CH / 8)) {
        const int pw = tid >> 5;         // / 32
        const int c8 = tid & 31;         // % 32 : which 8-channel chunk

        float2 best[4];
#pragma unroll
        for (int j = 0; j < 4; j++) best[j] = make_float2(-3.0e38f, -3.0e38f);

#pragma unroll
        for (int sy = 0; sy < SUBS; sy++) {
            const int   iu  = s_iu[sy];
            const int   idn = s_idn[sy];
            const float fy  = s_fy[sy];
#pragma unroll
            for (int sx = 0; sx < SUBS; sx++) {
                const int   xs = pw * SUBS + sx;
                const int   il = s_il[xs];
                const int   ir = s_ir[xs];
                const float fx = s_fx[xs];

                const uint4 h_ul = *((const uint4*)&g_featTh[((size_t)iu  * WF + il) * CH] + c8);
                const uint4 h_ur = *((const uint4*)&g_featTh[((size_t)iu  * WF + ir) * CH] + c8);
                const uint4 h_dl = *((const uint4*)&g_featTh[((size_t)idn * WF + il) * CH] + c8);
                const uint4 h_dr = *((const uint4*)&g_featTh[((size_t)idn * WF + ir) * CH] + c8);

                const float w_ul = (1.0f - fy) * (1.0f - fx);
                const float w_dl = fy * (1.0f - fx);
                const float w_ur = (1.0f - fy) * fx;
                const float w_dr = fy * fx;

                const unsigned* u_ul = (const unsigned*)&h_ul;
                const unsigned* u_ur = (const unsigned*)&h_ur;
                const unsigned* u_dl = (const unsigned*)&h_dl;
                const unsigned* u_dr = (const unsigned*)&h_dr;

#pragma unroll
                for (int j = 0; j < 4; j++) {
                    const float2 ful = __half22float2(*(const __half2*)&u_ul[j]);
                    const float2 fur = __half22float2(*(const __half2*)&u_ur[j]);
                    const float2 fdl = __half22float2(*(const __half2*)&u_dl[j]);
                    const float2 fdr = __half22float2(*(const __half2*)&u_dr[j]);
                    float vx = ful.x * w_ul + fdl.x * w_dl + fur.x * w_ur + fdr.x * w_dr;
                    float vy = ful.y * w_ul + fdl.y * w_dl + fur.y * w_ur + fdr.y * w_dr;
                    best[j].x = fmaxf(best[j].x, vx);
                    best[j].y = fmaxf(best[j].y, vy);
                }
            }
        }

        const int c = c8 * 8;
#pragma unroll
        for (int j = 0; j < 4; j++) {
            s_out[pw][c + 2 * j + 0] = best[j].x;
            s_out[pw][c + 2 * j + 1] = best[j].y;
        }
    }
    __syncthreads();

    // --- staged writeback: out[((n*CH + c)*HO + ph)*WO + pw] ---
    float* outp = out + ((size_t)n * CH * HO + ph) * WO;
    for (int i = tid; i < CH * WO; i += 256) {
        const int c  = i / WO;
        const int pw = i - c * WO;
        outp[(size_t)c * (HO * WO) + pw] = s_out[pw][c];
    }
}

extern "C" void kernel_launch(void* const* d_in, const int* in_sizes, int n_in,
                              void* d_out, int out_size) {
    const float* features = (const float*)d_in[0];  // (1, 256, 200, 200)
    const float* rois     = (const float*)d_in[1];  // (512, 4)
    const float* img_size = (const float*)d_in[2];  // (2,)
    float* out = (float*)d_out;                     // (512, 256, 7, 7)

    const int n_rois = in_sizes[1] / 4;

    dim3 tgrid(HF * WF / 32, CH / 32);
    dim3 tblock(32, 8);
    transpose_kernel<<<tgrid, tblock>>>(features);

    dim3 rgrid(n_rois, HO);
    roialign_kernel<<<rgrid, 256>>>(rois, img_size, out);
}